// round 2
// baseline (speedup 1.0000x reference)
#include <cuda_runtime.h>
#include <math.h>

#define cB 32
#define cS 145
#define cC 768
#define cD 8192
#define cSN 64
#define MPAD 160

__device__ float g_se1[cB*cC];
__device__ float g_a1[cB*cD];
__device__ float g_a2[cB*cD];
__device__ float g_u1[cD];
__device__ float g_u2[cD];
__device__ float g_q0[cB*cD];
__device__ float g_q1[cB*cD];
__device__ float g_q2[cD];
__device__ float g_A[3*cB*MPAD];
__device__ float g_s1f[cC], g_s2f[cC], g_t1[cC], g_t2[cC];
__device__ int   g_flag;

__global__ void k_init(const int* __restrict__ s1, const int* __restrict__ s2,
                       const float* __restrict__ tok)
{
    int idx = blockIdx.x*blockDim.x + threadIdx.x;
    int nt  = gridDim.x*blockDim.x;
    for (int i = idx; i < cB*cD; i += nt) { g_a1[i] = 0.f; g_a2[i] = 0.f; }
    for (int i = idx; i < cD;    i += nt) { g_u1[i] = 0.f; g_u2[i] = 0.f; }
    for (int i = idx; i < 3*cB*MPAD; i += nt) g_A[i] = 0.f;
    if (idx < cC) {
        float f1 = (float)s1[idx], f2 = (float)s2[idx];
        g_s1f[idx] = f1; g_s2f[idx] = f2;
        float t = tok[cC + idx];
        g_t1[idx] = t*f1; g_t2[idx] = t*f2;
    }
    if (idx == 0) g_flag = 0;
}

__global__ void k_se1(const float* __restrict__ sensor, const float* __restrict__ Wsen,
                      const float* __restrict__ bsen, const int* __restrict__ h1,
                      const int* __restrict__ h2, const float* __restrict__ b_s2)
{
    int b = blockIdx.x, tid = threadIdx.x;
    __shared__ float ss[cSN];
    if (tid < cSN) ss[tid] = sensor[b*cSN + tid];
    if (b == 0 && tid < cS && b_s2[tid] != 0.f) atomicOr(&g_flag, 1);
    __syncthreads();
    for (int c = tid; c < cC; c += blockDim.x) {
        float acc = bsen[c];
        const float* w = Wsen + c*cSN;
        #pragma unroll 16
        for (int n = 0; n < cSN; ++n) acc += ss[n]*w[n];
        g_se1[b*cC + c] = acc;
        float f1 = g_s1f[c], f2 = g_s2f[c];
        atomicAdd(&g_a1[b*cD + h1[c]], acc*f1);
        atomicAdd(&g_a2[b*cD + h2[c]], acc*f2);
        if (b == 0) { atomicAdd(&g_u1[h1[c]], f1); atomicAdd(&g_u2[h2[c]], f2); }
    }
}

// q0 = a1 (*) a2 ; if bias flag: q1 = a1(*)u2 + u1(*)a2 ; q2 = u1(*)u2
__global__ void k_conv(const int* __restrict__ h1, const int* __restrict__ h2)
{
    extern __shared__ float smc[];
    float* a1x  = smc;                  // 16384 doubled
    float* a2x  = smc + 16384;          // 16384 doubled (bias path)
    float* u1x  = smc + 32768;          // 16384 doubled (bias path)
    int*   psh2 = (int*)(smc + 49152);  // 768
    int*   psh1 = (int*)(smc + 49920);  // 768
    float* pv2  = smc + 50688;          // 768
    float* ps1  = smc + 51456;          // 768
    float* ps2  = smc + 52224;          // 768

    int b = blockIdx.x, tid = threadIdx.x;
    int flag = g_flag;
    for (int j = tid; j < cD; j += 1024) {
        float v = g_a1[b*cD + j]; a1x[j] = v; a1x[j + cD] = v;
        if (flag) {
            float v2 = g_a2[b*cD + j]; a2x[j] = v2; a2x[j + cD] = v2;
            float v3 = g_u1[j];        u1x[j] = v3; u1x[j + cD] = v3;
        }
    }
    if (tid < cC) {
        psh2[tid] = cD - h2[tid];
        psh1[tid] = cD - h1[tid];
        pv2[tid]  = g_se1[b*cC + tid]*g_s2f[tid];
        ps1[tid]  = g_s1f[tid];
        ps2[tid]  = g_s2f[tid];
    }
    __syncthreads();

    int d0 = blockIdx.y*2048 + tid, d1 = d0 + 1024;
    float q0a = 0.f, q0b = 0.f;
    if (!flag) {
        #pragma unroll 4
        for (int c = 0; c < cC; ++c) {
            int sh = psh2[c]; float v = pv2[c];
            q0a += v*a1x[d0 + sh];
            q0b += v*a1x[d1 + sh];
        }
        g_q0[b*cD + d0] = q0a; g_q0[b*cD + d1] = q0b;
    } else {
        float q1a = 0.f, q1b = 0.f, q2a = 0.f, q2b = 0.f;
        for (int c = 0; c < cC; ++c) {
            int s2v = psh2[c], s1v = psh1[c];
            float v = pv2[c], f1 = ps1[c], f2 = ps2[c];
            float ta0 = a1x[d0 + s2v], ta1 = a1x[d1 + s2v];
            q0a += v*ta0;                       q0b += v*ta1;
            q1a += f2*ta0 + f1*a2x[d0 + s1v];   q1b += f2*ta1 + f1*a2x[d1 + s1v];
            q2a += f2*u1x[d0 + s2v];            q2b += f2*u1x[d1 + s2v];
        }
        g_q0[b*cD + d0] = q0a; g_q0[b*cD + d1] = q0b;
        g_q1[b*cD + d0] = q1a; g_q1[b*cD + d1] = q1b;
        if (b == 0) { g_q2[d0] = q2a; g_q2[d1] = q2b; }
    }
}

// A_j[b,s] = sum_{c1,c2} xt1[s,c1] xt2[s,c2] q_j[(h1[c1]+h2[c2])&8191]
// grid (b, c2tile of 64, j); block (16,16); thread tile 10 s-rows x 4 c2-cols
__global__ __launch_bounds__(256) void k_quad(const float* __restrict__ img,
                                              const int* __restrict__ h1,
                                              const int* __restrict__ h2)
{
    extern __shared__ float smem[];
    float* sQ  = smem;                  // 8192
    float* sX1 = smem + 8192;           // 32*161
    float* sX2 = smem + 13344;          // 160*64
    int*   sH1 = (int*)(smem + 23584);  // 768
    float* sS1 = smem + 24352;
    float* sT1 = smem + 25120;
    float* sS2 = smem + 25888;
    float* sT2 = smem + 26656;          // total 27424 floats

    int z = blockIdx.z;
    if (z > 0 && g_flag == 0) return;
    int b = blockIdx.x, c2base = blockIdx.y*64;
    int tx = threadIdx.x, ty = threadIdx.y, tid = ty*16 + tx;

    const float* qsrc = (z == 0) ? (g_q0 + b*cD) : ((z == 1) ? (g_q1 + b*cD) : g_q2);
    for (int j = tid; j < cD; j += 256) sQ[j] = qsrc[j];
    for (int j = tid; j < cC; j += 256) {
        sH1[j] = h1[j];
        sS1[j] = g_s1f[j]; sT1[j] = g_t1[j];
        sS2[j] = g_s2f[j]; sT2[j] = g_t2[j];
    }
    __syncthreads();

    for (int e = tid; e < MPAD*64; e += 256) {
        int c2l = e & 63, s = e >> 6;
        int c2 = c2base + c2l;
        float v = 0.f;
        if (s < cS) v = img[(b*cS + s)*cC + c2]*sS2[c2] + sT2[c2];
        sX2[s*64 + c2l] = v;
    }

    int h2r[4];
    #pragma unroll
    for (int n = 0; n < 4; ++n) h2r[n] = h2[c2base + tx + 16*n];

    float acc[10][4];
    #pragma unroll
    for (int m = 0; m < 10; ++m)
        #pragma unroll
        for (int n = 0; n < 4; ++n) acc[m][n] = 0.f;

    for (int k0 = 0; k0 < cC; k0 += 32) {
        __syncthreads();
        #pragma unroll
        for (int i = 0; i < 20; ++i) {
            int e = tid + i*256;
            int kt = e & 31, s = e >> 5;
            int c1 = k0 + kt;
            float v = 0.f;
            if (s < cS) v = img[(b*cS + s)*cC + c1]*sS1[c1] + sT1[c1];
            sX1[kt*161 + s] = v;
        }
        __syncthreads();
        #pragma unroll 8
        for (int kt = 0; kt < 32; ++kt) {
            int h1v = sH1[k0 + kt];
            float x1r[10];
            #pragma unroll
            for (int m = 0; m < 10; ++m) x1r[m] = sX1[kt*161 + ty + 16*m];
            float qv[4];
            #pragma unroll
            for (int n = 0; n < 4; ++n) qv[n] = sQ[(h1v + h2r[n]) & (cD - 1)];
            #pragma unroll
            for (int m = 0; m < 10; ++m)
                #pragma unroll
                for (int n = 0; n < 4; ++n)
                    acc[m][n] += x1r[m]*qv[n];
        }
    }

    #pragma unroll
    for (int m = 0; m < 10; ++m) {
        int s = ty + 16*m;
        float al = 0.f;
        #pragma unroll
        for (int n = 0; n < 4; ++n) al += acc[m][n]*sX2[s*64 + tx + 16*n];
        atomicAdd(&g_A[(z*cB + b)*MPAD + s], al);
    }
}

__global__ void k_final(const float* __restrict__ W_s2, const float* __restrict__ b_s2,
                        const float* __restrict__ W_out, const float* __restrict__ b_out,
                        float* __restrict__ out)
{
    int tid = threadIdx.x;
    int b = tid >> 5, lane = tid & 31;
    float bpv[5]; float ssum = 0.f;
    #pragma unroll
    for (int i = 0; i < 5; ++i) {
        int s = lane + 32*i;
        float bp = 0.f;
        if (s < cS) {
            float w = W_s2[s], be = b_s2[s];
            float ip = w*w*g_A[b*MPAD + s]
                     + w*be*g_A[(cB + b)*MPAD + s]
                     + be*be*g_A[(2*cB + b)*MPAD + s];
            float sg = (ip > 0.f) ? 1.f : ((ip < 0.f) ? -1.f : 0.f);
            bp = sg*sqrtf(fabsf(ip) + 1e-5f);
        }
        bpv[i] = bp;
        ssum += bp*bp;
    }
    for (int o = 16; o > 0; o >>= 1) ssum += __shfl_xor_sync(0xffffffffu, ssum, o);
    float norm = fmaxf(sqrtf(ssum), 1e-12f);
    float acc = 0.f;
    #pragma unroll
    for (int i = 0; i < 5; ++i) {
        int s = lane + 32*i;
        if (s < cS) acc += bpv[i]*W_out[s];
    }
    for (int o = 16; o > 0; o >>= 1) acc += __shfl_xor_sync(0xffffffffu, acc, o);
    if (lane == 0) out[b] = acc/norm + b_out[0];
}

extern "C" void kernel_launch(void* const* d_in, const int* in_sizes, int n_in,
                              void* d_out, int out_size)
{
    // order: sensor, image_embeds, image_masks, h1, h2, s1, s2, [d],
    //        W_sensor, b_sensor, W_s2, b_s2, W_out, b_out, tok_emb
    int base = (in_sizes[7] == 1) ? 8 : 7;   // scalar 'd' may be omitted
    const float* sensor = (const float*)d_in[0];
    const float* img    = (const float*)d_in[1];
    const int*   h1     = (const int*)  d_in[3];
    const int*   h2     = (const int*)  d_in[4];
    const int*   s1     = (const int*)  d_in[5];
    const int*   s2     = (const int*)  d_in[6];
    const float* Wsen   = (const float*)d_in[base+0];
    const float* bsen   = (const float*)d_in[base+1];
    const float* Ws2    = (const float*)d_in[base+2];
    const float* bs2    = (const float*)d_in[base+3];
    const float* Wout   = (const float*)d_in[base+4];
    const float* bout   = (const float*)d_in[base+5];
    const float* tok    = (const float*)d_in[base+6];
    float* out = (float*)d_out;

    static int cfg = 0;
    if (!cfg) {
        cudaFuncSetAttribute(k_conv, cudaFuncAttributeMaxDynamicSharedMemorySize, 52992*4);
        cudaFuncSetAttribute(k_quad, cudaFuncAttributeMaxDynamicSharedMemorySize, 27424*4);
        cfg = 1;
    }

    k_init<<<256, 256>>>(s1, s2, tok);
    k_se1<<<cB, 256>>>(sensor, Wsen, bsen, h1, h2, bs2);
    k_conv<<<dim3(cB, 4), 1024, 52992*4>>>(h1, h2);
    k_quad<<<dim3(cB, 12, 3), dim3(16, 16), 27424*4>>>(img, h1, h2);
    k_final<<<1, 1024>>>(Ws2, bs2, Wout, bout, out);
}

// round 3
// speedup vs baseline: 1.7094x; 1.7094x over previous
#include <cuda_runtime.h>
#include <math.h>

#define cB 32
#define cS 145
#define cC 768
#define cD 8192
#define cSN 64
#define MPAD 160

__device__ float g_se1[cB*cC];
__device__ float g_a1[cB*cD];
__device__ float g_a2[cB*cD];
__device__ float g_u1[cD];
__device__ float g_u2[cD];
__device__ float g_q0[cB*cD];
__device__ float g_q1[cB*cD];
__device__ float g_q2[cD];
__device__ float g_A[3*cB*MPAD];
__device__ float g_s1f[cC], g_s2f[cC], g_t1[cC], g_t2[cC];
__device__ int   g_flag;
__device__ float g_x1[cB*MPAD*cC];   // tf32-rounded X1t, s padded to 160
__device__ float g_x2[cB*MPAD*cC];   // exact X2t

__device__ __forceinline__ unsigned int f2tf32(float f) {
    unsigned int u;
    asm("cvt.rna.tf32.f32 %0, %1;" : "=r"(u) : "f"(f));
    return u;
}

__global__ void k_init(const int* __restrict__ s1, const int* __restrict__ s2,
                       const float* __restrict__ tok)
{
    int idx = blockIdx.x*blockDim.x + threadIdx.x;
    int nt  = gridDim.x*blockDim.x;
    for (int i = idx; i < cB*cD; i += nt) { g_a1[i] = 0.f; g_a2[i] = 0.f; }
    for (int i = idx; i < cD;    i += nt) { g_u1[i] = 0.f; g_u2[i] = 0.f; }
    for (int i = idx; i < 3*cB*MPAD; i += nt) g_A[i] = 0.f;
    if (idx < cC) {
        float f1 = (float)s1[idx], f2 = (float)s2[idx];
        g_s1f[idx] = f1; g_s2f[idx] = f2;
        float t = tok[cC + idx];
        g_t1[idx] = t*f1; g_t2[idx] = t*f2;
    }
    if (idx == 0) g_flag = 0;
}

// X1t/X2t precompute; X1 rounded to tf32 so the GEMM A-stage is a pure copy
__global__ void k_prep(const float* __restrict__ img)
{
    int b = blockIdx.x, s = blockIdx.y;
    size_t o = (size_t)(b*MPAD + s)*cC;
    for (int c = threadIdx.x; c < cC; c += blockDim.x) {
        float v1 = 0.f, v2 = 0.f;
        if (s < cS) {
            float x = img[((size_t)b*cS + s)*cC + c];
            v1 = x*g_s1f[c] + g_t1[c];
            v2 = x*g_s2f[c] + g_t2[c];
        }
        unsigned int u = f2tf32(v1);
        g_x1[o + c] = __uint_as_float(u);
        g_x2[o + c] = v2;
    }
}

__global__ void k_se1(const float* __restrict__ sensor, const float* __restrict__ Wsen,
                      const float* __restrict__ bsen, const int* __restrict__ h1,
                      const int* __restrict__ h2, const float* __restrict__ b_s2)
{
    int b = blockIdx.x, tid = threadIdx.x;
    __shared__ float ss[cSN];
    if (tid < cSN) ss[tid] = sensor[b*cSN + tid];
    if (b == 0 && tid < cS && b_s2[tid] != 0.f) atomicOr(&g_flag, 1);
    __syncthreads();
    for (int c = tid; c < cC; c += blockDim.x) {
        float acc = bsen[c];
        const float* w = Wsen + c*cSN;
        #pragma unroll 16
        for (int n = 0; n < cSN; ++n) acc += ss[n]*w[n];
        g_se1[b*cC + c] = acc;
        float f1 = g_s1f[c], f2 = g_s2f[c];
        atomicAdd(&g_a1[b*cD + h1[c]], acc*f1);
        atomicAdd(&g_a2[b*cD + h2[c]], acc*f2);
        if (b == 0) { atomicAdd(&g_u1[h1[c]], f1); atomicAdd(&g_u2[h2[c]], f2); }
    }
}

// q0 = a1 (*) a2 ; if bias flag: q1 = a1(*)u2 + u1(*)a2 ; q2 = u1(*)u2
__global__ void k_conv(const int* __restrict__ h1, const int* __restrict__ h2)
{
    extern __shared__ float smc[];
    float* a1x  = smc;
    float* a2x  = smc + 16384;
    float* u1x  = smc + 32768;
    int*   psh2 = (int*)(smc + 49152);
    int*   psh1 = (int*)(smc + 49920);
    float* pv2  = smc + 50688;
    float* ps1  = smc + 51456;
    float* ps2  = smc + 52224;

    int b = blockIdx.x, tid = threadIdx.x;
    int flag = g_flag;
    for (int j = tid; j < cD; j += 1024) {
        float v = g_a1[b*cD + j]; a1x[j] = v; a1x[j + cD] = v;
        if (flag) {
            float v2 = g_a2[b*cD + j]; a2x[j] = v2; a2x[j + cD] = v2;
            float v3 = g_u1[j];        u1x[j] = v3; u1x[j + cD] = v3;
        }
    }
    if (tid < cC) {
        psh2[tid] = cD - h2[tid];
        psh1[tid] = cD - h1[tid];
        pv2[tid]  = g_se1[b*cC + tid]*g_s2f[tid];
        ps1[tid]  = g_s1f[tid];
        ps2[tid]  = g_s2f[tid];
    }
    __syncthreads();

    int d0 = blockIdx.y*2048 + tid, d1 = d0 + 1024;
    float q0a = 0.f, q0b = 0.f;
    if (!flag) {
        #pragma unroll 4
        for (int c = 0; c < cC; ++c) {
            int sh = psh2[c]; float v = pv2[c];
            q0a += v*a1x[d0 + sh];
            q0b += v*a1x[d1 + sh];
        }
        g_q0[b*cD + d0] = q0a; g_q0[b*cD + d1] = q0b;
    } else {
        float q1a = 0.f, q1b = 0.f, q2a = 0.f, q2b = 0.f;
        for (int c = 0; c < cC; ++c) {
            int s2v = psh2[c], s1v = psh1[c];
            float v = pv2[c], f1 = ps1[c], f2 = ps2[c];
            float ta0 = a1x[d0 + s2v], ta1 = a1x[d1 + s2v];
            q0a += v*ta0;                       q0b += v*ta1;
            q1a += f2*ta0 + f1*a2x[d0 + s1v];   q1b += f2*ta1 + f1*a2x[d1 + s1v];
            q2a += f2*u1x[d0 + s2v];            q2b += f2*u1x[d1 + s2v];
        }
        g_q0[b*cD + d0] = q0a; g_q0[b*cD + d1] = q0b;
        g_q1[b*cD + d0] = q1a; g_q1[b*cD + d1] = q1b;
        if (b == 0) { g_q2[d0] = q2a; g_q2[d1] = q2b; }
    }
}

// ---------------- tensor-core quad (z=0 / q0 term) -------------------------
// grid (b, c2tile of 64). CTA: M=160(s) x N=64(c2), K=768 in steps of 32.
// G tile gathered from tf32-rounded sQ; mma.sync.m16n8k8.tf32.
#define SQ_OFF   0
#define SA_OFF   8192            // [160][36]
#define SB_OFF   (8192+5760)     // [64][36]
#define SRED_OFF (8192+5760+2304)
#define SH1_OFF  (SRED_OFF+160)  // int[768]
#define SH2_OFF  (SH1_OFF+768)   // int[64]
#define SMEM_Q   (SH2_OFF+64)    // 17248 floats = 68992 B

__global__ __launch_bounds__(256) void k_quad_mma(const int* __restrict__ h1,
                                                  const int* __restrict__ h2)
{
    extern __shared__ float sm[];
    float* sQ = sm + SQ_OFF;
    float* sA = sm + SA_OFF;
    float* sB = sm + SB_OFF;
    float* sRed = sm + SRED_OFF;
    int* sH1 = (int*)(sm + SH1_OFF);
    int* sH2 = (int*)(sm + SH2_OFF);

    int b = blockIdx.x, c2base = blockIdx.y*64;
    int tid = threadIdx.x, lane = tid & 31, warp = tid >> 5;
    int wm = warp & 1, wn = warp >> 1;       // 2 x 4 warp grid

    const float* qsrc = g_q0 + b*cD;
    for (int j = tid; j < cD; j += 256) sQ[j] = __uint_as_float(f2tf32(qsrc[j]));
    for (int j = tid; j < cC; j += 256) sH1[j] = h1[j];
    if (tid < 64) sH2[tid] = h2[c2base + tid];
    if (tid < MPAD) sRed[tid] = 0.f;
    __syncthreads();

    float acc[5][2][4];
    #pragma unroll
    for (int mi = 0; mi < 5; ++mi)
        #pragma unroll
        for (int ni = 0; ni < 2; ++ni)
            #pragma unroll
            for (int j = 0; j < 4; ++j) acc[mi][ni][j] = 0.f;

    const float* x1p = g_x1 + (size_t)b*MPAD*cC;
    const unsigned int* sAu = (const unsigned int*)sA;
    const unsigned int* sBu = (const unsigned int*)sB;

    for (int k0 = 0; k0 < cC; k0 += 32) {
        __syncthreads();
        // stage A: [160][32] -> sA[s][36], float4
        #pragma unroll
        for (int i = 0; i < 5; ++i) {
            int e = tid + i*256;             // 1280 float4 slots
            int s = e >> 3, kq = e & 7;
            float4 v = *(const float4*)(x1p + (size_t)s*cC + k0 + kq*4);
            *(float4*)(sA + s*36 + kq*4) = v;
        }
        // gather B: sB[c2][k] = sQ[(h1[k0+k]+h2[c2]) & 8191]
        #pragma unroll
        for (int i = 0; i < 8; ++i) {
            int e = tid + i*256;             // 2048 slots
            int k = e & 31, c2l = e >> 5;
            sB[c2l*36 + k] = sQ[(sH1[k0 + k] + sH2[c2l]) & (cD - 1)];
        }
        __syncthreads();
        #pragma unroll
        for (int kb = 0; kb < 32; kb += 8) {
            unsigned int bf[2][2];
            #pragma unroll
            for (int ni = 0; ni < 2; ++ni) {
                int n0 = wn*16 + ni*8 + (lane >> 2);
                bf[ni][0] = sBu[n0*36 + kb + (lane & 3)];
                bf[ni][1] = sBu[n0*36 + kb + (lane & 3) + 4];
            }
            #pragma unroll
            for (int mi = 0; mi < 5; ++mi) {
                int r = wm*80 + mi*16 + (lane >> 2);
                unsigned int a0 = sAu[r*36 + kb + (lane & 3)];
                unsigned int a1 = sAu[(r+8)*36 + kb + (lane & 3)];
                unsigned int a2 = sAu[r*36 + kb + (lane & 3) + 4];
                unsigned int a3 = sAu[(r+8)*36 + kb + (lane & 3) + 4];
                #pragma unroll
                for (int ni = 0; ni < 2; ++ni) {
                    asm volatile(
                        "mma.sync.aligned.m16n8k8.row.col.f32.tf32.tf32.f32 "
                        "{%0,%1,%2,%3}, {%4,%5,%6,%7}, {%8,%9}, {%0,%1,%2,%3};"
                        : "+f"(acc[mi][ni][0]), "+f"(acc[mi][ni][1]),
                          "+f"(acc[mi][ni][2]), "+f"(acc[mi][ni][3])
                        : "r"(a0), "r"(a1), "r"(a2), "r"(a3),
                          "r"(bf[ni][0]), "r"(bf[ni][1]));
                }
            }
        }
    }

    // epilogue: fold with exact X2 (L1-resident LDG), reduce per s
    __syncthreads();
    const float* x2p = g_x2 + (size_t)b*MPAD*cC;
    #pragma unroll
    for (int mi = 0; mi < 5; ++mi) {
        int r0 = wm*80 + mi*16 + (lane >> 2);
        int r1 = r0 + 8;
        float s0 = 0.f, s1 = 0.f;
        #pragma unroll
        for (int ni = 0; ni < 2; ++ni) {
            int col = c2base + wn*16 + ni*8 + 2*(lane & 3);
            float2 xa = *(const float2*)(x2p + (size_t)r0*cC + col);
            float2 xb = *(const float2*)(x2p + (size_t)r1*cC + col);
            s0 += acc[mi][ni][0]*xa.x + acc[mi][ni][1]*xa.y;
            s1 += acc[mi][ni][2]*xb.x + acc[mi][ni][3]*xb.y;
        }
        atomicAdd(&sRed[r0], s0);
        atomicAdd(&sRed[r1], s1);
    }
    __syncthreads();
    if (tid < MPAD) atomicAdd(&g_A[b*MPAD + tid], sRed[tid]);
}

// ---------------- fallback quad for bias terms (z=1,2), active only if flag -
__global__ __launch_bounds__(256) void k_quad_bias(const float* __restrict__ img,
                                                   const int* __restrict__ h1,
                                                   const int* __restrict__ h2)
{
    extern __shared__ float smem[];
    float* sQ  = smem;
    float* sX1 = smem + 8192;
    float* sX2 = smem + 13344;
    int*   sH1 = (int*)(smem + 23584);
    float* sS1 = smem + 24352;
    float* sT1 = smem + 25120;
    float* sS2 = smem + 25888;
    float* sT2 = smem + 26656;

    if (g_flag == 0) return;
    int z = blockIdx.z + 1;
    int b = blockIdx.x, c2base = blockIdx.y*64;
    int tx = threadIdx.x, ty = threadIdx.y, tid = ty*16 + tx;

    const float* qsrc = (z == 1) ? (g_q1 + b*cD) : g_q2;
    for (int j = tid; j < cD; j += 256) sQ[j] = qsrc[j];
    for (int j = tid; j < cC; j += 256) {
        sH1[j] = h1[j];
        sS1[j] = g_s1f[j]; sT1[j] = g_t1[j];
        sS2[j] = g_s2f[j]; sT2[j] = g_t2[j];
    }
    __syncthreads();

    for (int e = tid; e < MPAD*64; e += 256) {
        int c2l = e & 63, s = e >> 6;
        int c2 = c2base + c2l;
        float v = 0.f;
        if (s < cS) v = img[(b*cS + s)*cC + c2]*sS2[c2] + sT2[c2];
        sX2[s*64 + c2l] = v;
    }

    int h2r[4];
    #pragma unroll
    for (int n = 0; n < 4; ++n) h2r[n] = h2[c2base + tx + 16*n];

    float acc[10][4];
    #pragma unroll
    for (int m = 0; m < 10; ++m)
        #pragma unroll
        for (int n = 0; n < 4; ++n) acc[m][n] = 0.f;

    for (int k0 = 0; k0 < cC; k0 += 32) {
        __syncthreads();
        #pragma unroll
        for (int i = 0; i < 20; ++i) {
            int e = tid + i*256;
            int kt = e & 31, s = e >> 5;
            int c1 = k0 + kt;
            float v = 0.f;
            if (s < cS) v = img[(b*cS + s)*cC + c1]*sS1[c1] + sT1[c1];
            sX1[kt*161 + s] = v;
        }
        __syncthreads();
        #pragma unroll 8
        for (int kt = 0; kt < 32; ++kt) {
            int h1v = sH1[k0 + kt];
            float x1r[10];
            #pragma unroll
            for (int m = 0; m < 10; ++m) x1r[m] = sX1[kt*161 + ty + 16*m];
            float qv[4];
            #pragma unroll
            for (int n = 0; n < 4; ++n) qv[n] = sQ[(h1v + h2r[n]) & (cD - 1)];
            #pragma unroll
            for (int m = 0; m < 10; ++m)
                #pragma unroll
                for (int n = 0; n < 4; ++n)
                    acc[m][n] += x1r[m]*qv[n];
        }
    }

    #pragma unroll
    for (int m = 0; m < 10; ++m) {
        int s = ty + 16*m;
        float al = 0.f;
        #pragma unroll
        for (int n = 0; n < 4; ++n) al += acc[m][n]*sX2[s*64 + tx + 16*n];
        atomicAdd(&g_A[(z*cB + b)*MPAD + s], al);
    }
}

__global__ void k_final(const float* __restrict__ W_s2, const float* __restrict__ b_s2,
                        const float* __restrict__ W_out, const float* __restrict__ b_out,
                        float* __restrict__ out)
{
    int tid = threadIdx.x;
    int b = tid >> 5, lane = tid & 31;
    float bpv[5]; float ssum = 0.f;
    #pragma unroll
    for (int i = 0; i < 5; ++i) {
        int s = lane + 32*i;
        float bp = 0.f;
        if (s < cS) {
            float w = W_s2[s], be = b_s2[s];
            float ip = w*w*g_A[b*MPAD + s]
                     + w*be*g_A[(cB + b)*MPAD + s]
                     + be*be*g_A[(2*cB + b)*MPAD + s];
            float sg = (ip > 0.f) ? 1.f : ((ip < 0.f) ? -1.f : 0.f);
            bp = sg*sqrtf(fabsf(ip) + 1e-5f);
        }
        bpv[i] = bp;
        ssum += bp*bp;
    }
    for (int o = 16; o > 0; o >>= 1) ssum += __shfl_xor_sync(0xffffffffu, ssum, o);
    float norm = fmaxf(sqrtf(ssum), 1e-12f);
    float acc = 0.f;
    #pragma unroll
    for (int i = 0; i < 5; ++i) {
        int s = lane + 32*i;
        if (s < cS) acc += bpv[i]*W_out[s];
    }
    for (int o = 16; o > 0; o >>= 1) acc += __shfl_xor_sync(0xffffffffu, acc, o);
    if (lane == 0) out[b] = acc/norm + b_out[0];
}

extern "C" void kernel_launch(void* const* d_in, const int* in_sizes, int n_in,
                              void* d_out, int out_size)
{
    int base = (in_sizes[7] == 1) ? 8 : 7;
    const float* sensor = (const float*)d_in[0];
    const float* img    = (const float*)d_in[1];
    const int*   h1     = (const int*)  d_in[3];
    const int*   h2     = (const int*)  d_in[4];
    const int*   s1     = (const int*)  d_in[5];
    const int*   s2     = (const int*)  d_in[6];
    const float* Wsen   = (const float*)d_in[base+0];
    const float* bsen   = (const float*)d_in[base+1];
    const float* Ws2    = (const float*)d_in[base+2];
    const float* bs2    = (const float*)d_in[base+3];
    const float* Wout   = (const float*)d_in[base+4];
    const float* bout   = (const float*)d_in[base+5];
    const float* tok    = (const float*)d_in[base+6];
    float* out = (float*)d_out;

    static int cfg = 0;
    if (!cfg) {
        cudaFuncSetAttribute(k_conv, cudaFuncAttributeMaxDynamicSharedMemorySize, 52992*4);
        cudaFuncSetAttribute(k_quad_mma, cudaFuncAttributeMaxDynamicSharedMemorySize, SMEM_Q*4);
        cudaFuncSetAttribute(k_quad_bias, cudaFuncAttributeMaxDynamicSharedMemorySize, 27424*4);
        cfg = 1;
    }

    k_init<<<256, 256>>>(s1, s2, tok);
    k_prep<<<dim3(cB, MPAD), 256>>>(img);
    k_se1<<<cB, 256>>>(sensor, Wsen, bsen, h1, h2, bs2);
    k_conv<<<dim3(cB, 4), 1024, 52992*4>>>(h1, h2);
    k_quad_mma<<<dim3(cB, 12), 256, SMEM_Q*4>>>(h1, h2);
    k_quad_bias<<<dim3(cB, 12, 2), dim3(16, 16), 27424*4>>>(img, h1, h2);
    k_final<<<1, 1024>>>(Ws2, bs2, Wout, bout, out);
}

// round 4
// speedup vs baseline: 1.7674x; 1.0339x over previous
#include <cuda_runtime.h>
#include <math.h>

#define cB 32
#define cS 145
#define cC 768
#define cD 8192
#define cSN 64
#define MPAD 160

__device__ float g_se1[cB*cC];
__device__ float g_a1[cB*cD];
__device__ float g_a2[cB*cD];
__device__ float g_u1[cD];
__device__ float g_u2[cD];
__device__ float g_q0[cB*cD];
__device__ float g_q1[cB*cD];
__device__ float g_q2[cD];
__device__ float g_A[3*cB*MPAD];
__device__ int   g_flag;
__device__ float g_x1[cB*MPAD*cC];   // tf32-rounded X1t, k-permuted within 8-groups
__device__ float g_x2[cB*MPAD*cC];   // exact X2t

__device__ __forceinline__ unsigned int f2tf32(float f) {
    unsigned int u;
    asm("cvt.rna.tf32.f32 %0, %1;" : "=r"(u) : "f"(f));
    return u;
}

// ---------------- k_init: zero scratch only --------------------------------
__global__ void k_init()
{
    int idx = blockIdx.x*blockDim.x + threadIdx.x;
    int nt  = gridDim.x*blockDim.x;
    for (int i = idx; i < cB*cD; i += nt) { g_a1[i] = 0.f; g_a2[i] = 0.f; }
    for (int i = idx; i < cD;    i += nt) { g_u1[i] = 0.f; g_u2[i] = 0.f; }
    for (int i = idx; i < 3*cB*MPAD; i += nt) g_A[i] = 0.f;
    if (idx == 0) g_flag = 0;
}

// ---------------- k_prep: X1 (tf32, permuted) and X2 (exact) ---------------
__global__ void k_prep(const float* __restrict__ img, const float* __restrict__ tok,
                       const int* __restrict__ s1, const int* __restrict__ s2)
{
    int b = blockIdx.x, s = blockIdx.y;
    size_t o = (size_t)(b*MPAD + s)*cC;
    for (int c = threadIdx.x; c < cC; c += blockDim.x) {
        float f1 = (float)s1[c], f2 = (float)s2[c];
        float v = 0.f;
        if (s < cS) v = img[((size_t)b*cS + s)*cC + c] + tok[cC + c];
        int cp = (c & ~7) | (((c & 3) << 1) | ((c & 7) >> 2));   // sp(k)
        g_x1[o + cp] = __uint_as_float(f2tf32(v*f1));
        g_x2[o + c]  = v*f2;
    }
}

// ---------------- k_se1: sensor GEMV + sketch scatter + bias flag ----------
__global__ void k_se1(const float* __restrict__ sensor, const float* __restrict__ Wsen,
                      const float* __restrict__ bsen, const int* __restrict__ h1,
                      const int* __restrict__ h2, const float* __restrict__ b_s2,
                      const int* __restrict__ s1, const int* __restrict__ s2)
{
    int b = blockIdx.x, tid = threadIdx.x;
    __shared__ float ss[cSN];
    if (tid < cSN) ss[tid] = sensor[b*cSN + tid];
    if (b == 0 && tid < cS && b_s2[tid] != 0.f) atomicOr(&g_flag, 1);
    __syncthreads();
    for (int c = tid; c < cC; c += blockDim.x) {
        float acc = bsen[c];
        const float* w = Wsen + c*cSN;
        #pragma unroll 16
        for (int n = 0; n < cSN; ++n) acc += ss[n]*w[n];
        g_se1[b*cC + c] = acc;
        float f1 = (float)s1[c], f2 = (float)s2[c];
        atomicAdd(&g_a1[b*cD + h1[c]], acc*f1);
        atomicAdd(&g_a2[b*cD + h2[c]], acc*f2);
        if (b == 0) { atomicAdd(&g_u1[h1[c]], f1); atomicAdd(&g_u2[h2[c]], f2); }
    }
}

// ---------------- k_conv: fast path, q0 only -------------------------------
// grid (cB, 8), 256 threads, 4 d-values per thread. smem = a1x(16384) + pt(768 f2)
__global__ __launch_bounds__(256) void k_conv(const int* __restrict__ h2,
                                              const int* __restrict__ s2)
{
    extern __shared__ float smc[];
    float*  a1x = smc;
    float2* pt  = (float2*)(smc + 16384);

    int b = blockIdx.x, tid = threadIdx.x;
    for (int j = tid; j < cD; j += 256) {
        float v = g_a1[b*cD + j]; a1x[j] = v; a1x[j + cD] = v;
    }
    for (int c = tid; c < cC; c += 256) {
        pt[c] = make_float2(__int_as_float(cD - h2[c]),
                            g_se1[b*cC + c]*(float)s2[c]);
    }
    __syncthreads();

    int d0 = blockIdx.y*1024 + tid;
    float q0 = 0.f, q1 = 0.f, q2 = 0.f, q3 = 0.f;
    #pragma unroll 4
    for (int c = 0; c < cC; ++c) {
        float2 p = pt[c];
        int base = d0 + __float_as_int(p.x);
        q0 += p.y*a1x[base];
        q1 += p.y*a1x[base + 256];
        q2 += p.y*a1x[base + 512];
        q3 += p.y*a1x[base + 768];
    }
    float* qo = g_q0 + b*cD + d0;
    qo[0] = q0; qo[256] = q1; qo[512] = q2; qo[768] = q3;
}

// ---------------- k_conv_bias: q1/q2 (only if bias nonzero) ----------------
__global__ void k_conv_bias(const int* __restrict__ h1, const int* __restrict__ h2,
                            const int* __restrict__ s1, const int* __restrict__ s2)
{
    extern __shared__ float smc[];
    float* a1x  = smc;
    float* a2x  = smc + 16384;
    float* u1x  = smc + 32768;
    int*   psh2 = (int*)(smc + 49152);
    int*   psh1 = (int*)(smc + 49920);
    float* pv2  = smc + 50688;
    float* ps1  = smc + 51456;
    float* ps2  = smc + 52224;

    if (g_flag == 0) return;
    int b = blockIdx.x, tid = threadIdx.x;
    for (int j = tid; j < cD; j += 1024) {
        float v  = g_a1[b*cD + j]; a1x[j] = v;  a1x[j + cD] = v;
        float v2 = g_a2[b*cD + j]; a2x[j] = v2; a2x[j + cD] = v2;
        float v3 = g_u1[j];        u1x[j] = v3; u1x[j + cD] = v3;
    }
    if (tid < cC) {
        psh2[tid] = cD - h2[tid];
        psh1[tid] = cD - h1[tid];
        float f2 = (float)s2[tid];
        pv2[tid]  = g_se1[b*cC + tid]*f2;
        ps1[tid]  = (float)s1[tid];
        ps2[tid]  = f2;
    }
    __syncthreads();

    int d0 = blockIdx.y*2048 + tid, d1 = d0 + 1024;
    float q1a = 0.f, q1b = 0.f, q2a = 0.f, q2b = 0.f;
    for (int c = 0; c < cC; ++c) {
        int s2v = psh2[c], s1v = psh1[c];
        float f1 = ps1[c], f2 = ps2[c];
        q1a += f2*a1x[d0 + s2v] + f1*a2x[d0 + s1v];
        q1b += f2*a1x[d1 + s2v] + f1*a2x[d1 + s1v];
        q2a += f2*u1x[d0 + s2v];
        q2b += f2*u1x[d1 + s2v];
    }
    g_q1[b*cD + d0] = q1a; g_q1[b*cD + d1] = q1b;
    if (b == 0) { g_q2[d0] = q2a; g_q2[d1] = q2b; }
}

// ---------------- tensor-core quad (q0 term) -------------------------------
// 8 warps = 2(M) x 2(N) x 2(K-split); warp tile 80x32; double-buffered k-tiles
#define STR 40
#define SQ_OFF   0
#define SA_OFF   8192                 // 2 x 160*40
#define SB_OFF   (SA_OFF + 12800)     // 2 x 64*40
#define SRED_OFF (SB_OFF + 5120)      // 160
#define SH1_OFF  (SRED_OFF + 160)     // int 768
#define SH2_OFF  (SH1_OFF + 768)     // int 64
#define SMEM_Q   (SH2_OFF + 64)      // 27104 floats

__global__ __launch_bounds__(256, 1) void k_quad_mma(const int* __restrict__ h1,
                                                     const int* __restrict__ h2)
{
    extern __shared__ float sm[];
    float* sQ   = sm + SQ_OFF;
    float* sRed = sm + SRED_OFF;
    int* sH1p = (int*)(sm + SH1_OFF);
    int* sH2  = (int*)(sm + SH2_OFF);

    int b = blockIdx.x, c2base = blockIdx.y*64;
    int tid = threadIdx.x, lane = tid & 31, warp = tid >> 5;
    int wm = warp & 1, wn = (warp >> 1) & 1, wk = warp >> 2;
    int t4 = lane & 3, qr = lane >> 2;

    const float* qsrc = g_q0 + b*cD;
    for (int j = tid; j < cD; j += 256) sQ[j] = __uint_as_float(f2tf32(qsrc[j]));
    for (int j = tid; j < cC; j += 256) {
        int p = j & 7;
        sH1p[j] = h1[(j & ~7) | (((p & 1) << 2) | (p >> 1))];   // invp
    }
    if (tid < 64)  sH2[tid] = h2[c2base + tid];
    if (tid < MPAD) sRed[tid] = 0.f;
    __syncthreads();

    float acc[5][4][4];
    #pragma unroll
    for (int mi = 0; mi < 5; ++mi)
        #pragma unroll
        for (int ni = 0; ni < 4; ++ni)
            #pragma unroll
            for (int j = 0; j < 4; ++j) acc[mi][ni][j] = 0.f;

    const float* x1p = g_x1 + (size_t)b*MPAD*cC;

    for (int r = 0; r < 12; ++r) {
        // stage A: two 160x32 tiles (k already permuted in global layout)
        #pragma unroll
        for (int i = 0; i < 10; ++i) {
            int e = tid + i*256;
            int s = e >> 4, kq = e & 15;
            float4 v = *(const float4*)(x1p + (size_t)s*cC + r*64 + kq*4);
            *(float4*)(sm + SA_OFF + (kq >> 3)*6400 + s*STR + (kq & 7)*4) = v;
        }
        // gather B: two 64x32 tiles
        #pragma unroll
        for (int i = 0; i < 16; ++i) {
            int e = tid + i*256;
            int p = e & 31, c2l = (e >> 5) & 63, tile = e >> 11;
            sm[SB_OFF + tile*2560 + c2l*STR + p] =
                sQ[(sH1p[r*64 + tile*32 + p] + sH2[c2l]) & (cD - 1)];
        }
        __syncthreads();

        const float* At = sm + SA_OFF + wk*6400;
        const float* Bt = sm + SB_OFF + wk*2560;
        #pragma unroll
        for (int kb = 0; kb < 32; kb += 8) {
            float2 bfr[4];
            #pragma unroll
            for (int ni = 0; ni < 4; ++ni) {
                int n0 = wn*32 + ni*8 + qr;
                bfr[ni] = *(const float2*)(Bt + n0*STR + kb + 2*t4);
            }
            #pragma unroll
            for (int mi = 0; mi < 5; ++mi) {
                int rr = wm*80 + mi*16 + qr;
                float2 aA = *(const float2*)(At + rr*STR + kb + 2*t4);
                float2 aB = *(const float2*)(At + (rr + 8)*STR + kb + 2*t4);
                unsigned int a0 = __float_as_uint(aA.x), a1r = __float_as_uint(aB.x);
                unsigned int a2 = __float_as_uint(aA.y), a3 = __float_as_uint(aB.y);
                #pragma unroll
                for (int ni = 0; ni < 4; ++ni) {
                    asm volatile(
                        "mma.sync.aligned.m16n8k8.row.col.f32.tf32.tf32.f32 "
                        "{%0,%1,%2,%3}, {%4,%5,%6,%7}, {%8,%9}, {%0,%1,%2,%3};"
                        : "+f"(acc[mi][ni][0]), "+f"(acc[mi][ni][1]),
                          "+f"(acc[mi][ni][2]), "+f"(acc[mi][ni][3])
                        : "r"(a0), "r"(a1r), "r"(a2), "r"(a3),
                          "r"(__float_as_uint(bfr[ni].x)), "r"(__float_as_uint(bfr[ni].y)));
                }
            }
        }
        __syncthreads();
    }

    // k-split reduction: wk1 -> scratch (reuse sA), wk0 adds + epilogue
    float* red = sm + SA_OFF;
    int pairId = wm*2 + wn;
    if (wk == 1) {
        float* dst = red + (pairId*32 + lane)*80;
        #pragma unroll
        for (int mi = 0; mi < 5; ++mi)
            #pragma unroll
            for (int ni = 0; ni < 4; ++ni)
                #pragma unroll
                for (int j = 0; j < 4; ++j) dst[mi*16 + ni*4 + j] = acc[mi][ni][j];
    }
    __syncthreads();
    if (wk == 0) {
        const float* src = red + (pairId*32 + lane)*80;
        #pragma unroll
        for (int mi = 0; mi < 5; ++mi)
            #pragma unroll
            for (int ni = 0; ni < 4; ++ni)
                #pragma unroll
                for (int j = 0; j < 4; ++j) acc[mi][ni][j] += src[mi*16 + ni*4 + j];

        const float* x2p = g_x2 + (size_t)b*MPAD*cC;
        #pragma unroll
        for (int mi = 0; mi < 5; ++mi) {
            int r0 = wm*80 + mi*16 + qr;
            int r1 = r0 + 8;
            float s0 = 0.f, s1v = 0.f;
            #pragma unroll
            for (int ni = 0; ni < 4; ++ni) {
                int col = c2base + wn*32 + ni*8 + 2*t4;
                float2 xa = *(const float2*)(x2p + (size_t)r0*cC + col);
                float2 xb = *(const float2*)(x2p + (size_t)r1*cC + col);
                s0  += acc[mi][ni][0]*xa.x + acc[mi][ni][1]*xa.y;
                s1v += acc[mi][ni][2]*xb.x + acc[mi][ni][3]*xb.y;
            }
            atomicAdd(&sRed[r0], s0);
            atomicAdd(&sRed[r1], s1v);
        }
    }
    __syncthreads();
    if (tid < MPAD) atomicAdd(&g_A[b*MPAD + tid], sRed[tid]);
}

// ---------------- fallback quad for bias terms (z=1,2) ---------------------
__global__ __launch_bounds__(256) void k_quad_bias(const float* __restrict__ img,
                                                   const int* __restrict__ h1,
                                                   const int* __restrict__ h2,
                                                   const float* __restrict__ tok,
                                                   const int* __restrict__ s1,
                                                   const int* __restrict__ s2)
{
    extern __shared__ float smem[];
    float* sQ  = smem;
    float* sX1 = smem + 8192;
    float* sX2 = smem + 13344;
    int*   sH1 = (int*)(smem + 23584);
    float* sS1 = smem + 24352;
    float* sS2 = smem + 25120;
    float* sTk = smem + 25888;

    if (g_flag == 0) return;
    int z = blockIdx.z + 1;
    int b = blockIdx.x, c2base = blockIdx.y*64;
    int tx = threadIdx.x, ty = threadIdx.y, tid = ty*16 + tx;

    const float* qsrc = (z == 1) ? (g_q1 + b*cD) : g_q2;
    for (int j = tid; j < cD; j += 256) sQ[j] = qsrc[j];
    for (int j = tid; j < cC; j += 256) {
        sH1[j] = h1[j];
        sS1[j] = (float)s1[j]; sS2[j] = (float)s2[j];
        sTk[j] = tok[cC + j];
    }
    __syncthreads();

    for (int e = tid; e < MPAD*64; e += 256) {
        int c2l = e & 63, s = e >> 6;
        int c2 = c2base + c2l;
        float v = 0.f;
        if (s < cS) v = (img[(b*cS + s)*cC + c2] + sTk[c2])*sS2[c2];
        sX2[s*64 + c2l] = v;
    }

    int h2r[4];
    #pragma unroll
    for (int n = 0; n < 4; ++n) h2r[n] = h2[c2base + tx + 16*n];

    float acc[10][4];
    #pragma unroll
    for (int m = 0; m < 10; ++m)
        #pragma unroll
        for (int n = 0; n < 4; ++n) acc[m][n] = 0.f;

    for (int k0 = 0; k0 < cC; k0 += 32) {
        __syncthreads();
        #pragma unroll
        for (int i = 0; i < 20; ++i) {
            int e = tid + i*256;
            int kt = e & 31, s = e >> 5;
            int c1 = k0 + kt;
            float v = 0.f;
            if (s < cS) v = (img[(b*cS + s)*cC + c1] + sTk[c1])*sS1[c1];
            sX1[kt*161 + s] = v;
        }
        __syncthreads();
        #pragma unroll 8
        for (int kt = 0; kt < 32; ++kt) {
            int h1v = sH1[k0 + kt];
            float x1r[10];
            #pragma unroll
            for (int m = 0; m < 10; ++m) x1r[m] = sX1[kt*161 + ty + 16*m];
            float qv[4];
            #pragma unroll
            for (int n = 0; n < 4; ++n) qv[n] = sQ[(h1v + h2r[n]) & (cD - 1)];
            #pragma unroll
            for (int m = 0; m < 10; ++m)
                #pragma unroll
                for (int n = 0; n < 4; ++n)
                    acc[m][n] += x1r[m]*qv[n];
        }
    }

    #pragma unroll
    for (int m = 0; m < 10; ++m) {
        int s = ty + 16*m;
        float al = 0.f;
        #pragma unroll
        for (int n = 0; n < 4; ++n) al += acc[m][n]*sX2[s*64 + tx + 16*n];
        atomicAdd(&g_A[(z*cB + b)*MPAD + s], al);
    }
}

__global__ void k_final(const float* __restrict__ W_s2, const float* __restrict__ b_s2,
                        const float* __restrict__ W_out, const float* __restrict__ b_out,
                        float* __restrict__ out)
{
    int tid = threadIdx.x;
    int b = tid >> 5, lane = tid & 31;
    float bpv[5]; float ssum = 0.f;
    #pragma unroll
    for (int i = 0; i < 5; ++i) {
        int s = lane + 32*i;
        float bp = 0.f;
        if (s < cS) {
            float w = W_s2[s], be = b_s2[s];
            float ip = w*w*g_A[b*MPAD + s]
                     + w*be*g_A[(cB + b)*MPAD + s]
                     + be*be*g_A[(2*cB + b)*MPAD + s];
            float sg = (ip > 0.f) ? 1.f : ((ip < 0.f) ? -1.f : 0.f);
            bp = sg*sqrtf(fabsf(ip) + 1e-5f);
        }
        bpv[i] = bp;
        ssum += bp*bp;
    }
    for (int o = 16; o > 0; o >>= 1) ssum += __shfl_xor_sync(0xffffffffu, ssum, o);
    float norm = fmaxf(sqrtf(ssum), 1e-12f);
    float acc = 0.f;
    #pragma unroll
    for (int i = 0; i < 5; ++i) {
        int s = lane + 32*i;
        if (s < cS) acc += bpv[i]*W_out[s];
    }
    for (int o = 16; o > 0; o >>= 1) acc += __shfl_xor_sync(0xffffffffu, acc, o);
    if (lane == 0) out[b] = acc/norm + b_out[0];
}

extern "C" void kernel_launch(void* const* d_in, const int* in_sizes, int n_in,
                              void* d_out, int out_size)
{
    int base = (in_sizes[7] == 1) ? 8 : 7;
    const float* sensor = (const float*)d_in[0];
    const float* img    = (const float*)d_in[1];
    const int*   h1     = (const int*)  d_in[3];
    const int*   h2     = (const int*)  d_in[4];
    const int*   s1     = (const int*)  d_in[5];
    const int*   s2     = (const int*)  d_in[6];
    const float* Wsen   = (const float*)d_in[base+0];
    const float* bsen   = (const float*)d_in[base+1];
    const float* Ws2    = (const float*)d_in[base+2];
    const float* bs2    = (const float*)d_in[base+3];
    const float* Wout   = (const float*)d_in[base+4];
    const float* bout   = (const float*)d_in[base+5];
    const float* tok    = (const float*)d_in[base+6];
    float* out = (float*)d_out;

    static int cfg = 0;
    if (!cfg) {
        cudaFuncSetAttribute(k_conv,      cudaFuncAttributeMaxDynamicSharedMemorySize, 17920*4);
        cudaFuncSetAttribute(k_conv_bias, cudaFuncAttributeMaxDynamicSharedMemorySize, 52992*4);
        cudaFuncSetAttribute(k_quad_mma,  cudaFuncAttributeMaxDynamicSharedMemorySize, SMEM_Q*4);
        cudaFuncSetAttribute(k_quad_bias, cudaFuncAttributeMaxDynamicSharedMemorySize, 27424*4);
        cfg = 1;
    }

    k_init<<<256, 256>>>();
    k_prep<<<dim3(cB, MPAD), 256>>>(img, tok, s1, s2);
    k_se1<<<cB, 256>>>(sensor, Wsen, bsen, h1, h2, bs2, s1, s2);
    k_conv<<<dim3(cB, 8), 256, 17920*4>>>(h2, s2);
    k_conv_bias<<<dim3(cB, 4), 1024, 52992*4>>>(h1, h2, s1, s2);
    k_quad_mma<<<dim3(cB, 12), 256, SMEM_Q*4>>>(h1, h2);
    k_quad_bias<<<dim3(cB, 12, 2), dim3(16, 16), 27424*4>>>(img, h1, h2, tok, s1, s2);
    k_final<<<1, 1024>>>(Ws2, bs2, Wout, bout, out);
}